// round 3
// baseline (speedup 1.0000x reference)
#include <cuda_runtime.h>

typedef unsigned long long u64;

// ---------- packed f32x2 helpers (Blackwell FFMA2 path) ----------
__device__ __forceinline__ u64 pk2(float lo, float hi) {
    u64 r;
    asm("mov.b64 %0, {%1, %2};" : "=l"(r)
        : "r"(__float_as_uint(lo)), "r"(__float_as_uint(hi)));
    return r;
}
__device__ __forceinline__ void upk(u64 a, float& lo, float& hi) {
    unsigned int l_, h_;
    asm("mov.b64 {%0, %1}, %2;" : "=r"(l_), "=r"(h_) : "l"(a));
    lo = __uint_as_float(l_);
    hi = __uint_as_float(h_);
}
__device__ __forceinline__ u64 dfma(u64 a, u64 b, u64 c) {
    u64 d;
    asm("fma.rn.f32x2 %0, %1, %2, %3;" : "=l"(d) : "l"(a), "l"(b), "l"(c));
    return d;
}
__device__ __forceinline__ u64 dmul(u64 a, u64 b) {
    u64 d;
    asm("mul.rn.f32x2 %0, %1, %2;" : "=l"(d) : "l"(a), "l"(b));
    return d;
}
__device__ __forceinline__ u64 dadd(u64 a, u64 b) {
    u64 d;
    asm("add.rn.f32x2 %0, %1, %2;" : "=l"(d) : "l"(a), "l"(b));
    return d;
}
// 2*relu(x) per half, exact: x + |x|  (2x folded into pre-halved W2/W3)
__device__ __forceinline__ u64 drelu2(u64 a) {
    return dadd(a, a & 0x7FFFFFFF7FFFFFFFULL);
}
// Pin a value into a register; forbids remat/spill-and-reload of the def.
#define PIN(x) asm volatile("" : "+l"(x))

// Process a packed pair of neighbors. Weight regs passed by (inlined) pointer.
// Layer-1 dot products use the UNNORMALIZED diff so they overlap the MUFU rsqrt:
//   h = relu((W1.d) * inv + b1);  vel += d * (inv * w)
__device__ __forceinline__ void pair_step(
    u64 ax, u64 ay, u64 az,
    u64 npx, u64 npy, u64 npz,
    const u64* w1, const u64* bb1,
    const u64* w2, const u64* bb2,   // w2 pre-scaled by 0.5
    const u64* w3, u64 bb3,          // w3 pre-scaled by 0.5
    u64& vx, u64& vy, u64& vz)
{
    u64 dx = dadd(ax, npx);
    u64 dy = dadd(ay, npy);
    u64 dz = dadd(az, npz);
    u64 d2 = dfma(dx, dx, dfma(dy, dy, dmul(dz, dz)));
    float a, b;
    upk(d2, a, b);
    float ia = rsqrtf(fmaxf(a, 1e-24f));   // matches v/max(||v||,1e-12)
    float ib = rsqrtf(fmaxf(b, 1e-24f));

    // W1 . d  (independent of the rsqrt -> overlaps MUFU latency)
    u64 u0 = dfma(dz, w1[2],  dfma(dy, w1[1],  dmul(dx, w1[0])));
    u64 u1 = dfma(dz, w1[5],  dfma(dy, w1[4],  dmul(dx, w1[3])));
    u64 u2 = dfma(dz, w1[8],  dfma(dy, w1[7],  dmul(dx, w1[6])));
    u64 u3 = dfma(dz, w1[11], dfma(dy, w1[10], dmul(dx, w1[9])));
    u64 u4 = dfma(dz, w1[14], dfma(dy, w1[13], dmul(dx, w1[12])));

    u64 inv = pk2(ia, ib);

    u64 h0 = drelu2(dfma(u0, inv, bb1[0]));
    u64 h1 = drelu2(dfma(u1, inv, bb1[1]));
    u64 h2 = drelu2(dfma(u2, inv, bb1[2]));
    u64 h3 = drelu2(dfma(u3, inv, bb1[3]));
    u64 h4 = drelu2(dfma(u4, inv, bb1[4]));

    // Layer 2 (weights pre-scaled by 0.5 to absorb the 2x from drelu2)
    u64 g0 = bb2[0], g1 = bb2[1], g2 = bb2[2], g3 = bb2[3], g4 = bb2[4];
    g0 = dfma(h0, w2[0],  g0); g0 = dfma(h1, w2[1],  g0); g0 = dfma(h2, w2[2],  g0);
    g0 = dfma(h3, w2[3],  g0); g0 = dfma(h4, w2[4],  g0);
    g1 = dfma(h0, w2[5],  g1); g1 = dfma(h1, w2[6],  g1); g1 = dfma(h2, w2[7],  g1);
    g1 = dfma(h3, w2[8],  g1); g1 = dfma(h4, w2[9],  g1);
    g2 = dfma(h0, w2[10], g2); g2 = dfma(h1, w2[11], g2); g2 = dfma(h2, w2[12], g2);
    g2 = dfma(h3, w2[13], g2); g2 = dfma(h4, w2[14], g2);
    g3 = dfma(h0, w2[15], g3); g3 = dfma(h1, w2[16], g3); g3 = dfma(h2, w2[17], g3);
    g3 = dfma(h3, w2[18], g3); g3 = dfma(h4, w2[19], g3);
    g4 = dfma(h0, w2[20], g4); g4 = dfma(h1, w2[21], g4); g4 = dfma(h2, w2[22], g4);
    g4 = dfma(h3, w2[23], g4); g4 = dfma(h4, w2[24], g4);
    g0 = drelu2(g0); g1 = drelu2(g1); g2 = drelu2(g2); g3 = drelu2(g3); g4 = drelu2(g4);

    // Layer 3 (pre-scaled by 0.5)
    u64 w = bb3;
    w = dfma(g0, w3[0], w); w = dfma(g1, w3[1], w); w = dfma(g2, w3[2], w);
    w = dfma(g3, w3[3], w); w = dfma(g4, w3[4], w);

    // vel += nd * w == d * (inv * w)
    u64 wi = dmul(w, inv);
    vx = dfma(dx, wi, vx);
    vy = dfma(dy, wi, vy);
    vz = dfma(dz, wi, vz);
}

__global__ void __launch_bounds__(128, 1)
velvec_kernel(const float* __restrict__ pos, const float* __restrict__ nbr,
              const float* __restrict__ W1, const float* __restrict__ b1,
              const float* __restrict__ W2, const float* __restrict__ b2,
              const float* __restrict__ W3, const float* __restrict__ b3,
              float* __restrict__ out, int N)
{
    int n = blockIdx.x * blockDim.x + threadIdx.x;
    if (n >= N) return;

    // Load + pack weights once; PIN each so they stay register-resident
    // across the mainloop (no LDC storm, no spill-reload).
    u64 w1[15], bb1[5], w2[25], bb2[5], w3[5];
#pragma unroll
    for (int i = 0; i < 15; i++) { float v = __ldg(W1 + i);        w1[i]  = pk2(v, v); PIN(w1[i]); }
#pragma unroll
    for (int i = 0; i < 5;  i++) { float v = __ldg(b1 + i);        bb1[i] = pk2(v, v); PIN(bb1[i]); }
#pragma unroll
    for (int i = 0; i < 25; i++) { float v = 0.5f * __ldg(W2 + i); w2[i]  = pk2(v, v); PIN(w2[i]); }
#pragma unroll
    for (int i = 0; i < 5;  i++) { float v = __ldg(b2 + i);        bb2[i] = pk2(v, v); PIN(bb2[i]); }
#pragma unroll
    for (int i = 0; i < 5;  i++) { float v = 0.5f * __ldg(W3 + i); w3[i]  = pk2(v, v); PIN(w3[i]); }
    float b3v = __ldg(b3);
    u64 bb3 = pk2(b3v, b3v); PIN(bb3);

    float px = pos[3 * n + 0];
    float py = pos[3 * n + 1];
    float pz = pos[3 * n + 2];
    u64 npx = pk2(-px, -px), npy = pk2(-py, -py), npz = pk2(-pz, -pz);

    u64 vx = 0ULL, vy = 0ULL, vz = 0ULL;  // (+0.f, +0.f)

    // 32 neighbors * 3 floats = 96 floats = 24 float4 per point (384B aligned).
    const float4* base = reinterpret_cast<const float4*>(nbr) + (size_t)n * 24;

#pragma unroll 2
    for (int g = 0; g < 8; g++) {
        float4 q0 = base[3 * g + 0];  // x0 y0 z0 x1
        float4 q1 = base[3 * g + 1];  // y1 z1 x2 y2
        float4 q2 = base[3 * g + 2];  // z2 x3 y3 z3
        pair_step(pk2(q0.x, q0.w), pk2(q0.y, q1.x), pk2(q0.z, q1.y),
                  npx, npy, npz, w1, bb1, w2, bb2, w3, bb3, vx, vy, vz);
        pair_step(pk2(q1.z, q2.y), pk2(q1.w, q2.z), pk2(q2.x, q2.w),
                  npx, npy, npz, w1, bb1, w2, bb2, w3, bb3, vx, vy, vz);
    }

    float x0, x1, y0, y1, z0, z1;
    upk(vx, x0, x1); upk(vy, y0, y1); upk(vz, z0, z1);
    float fx = x0 + x1, fy = y0 + y1, fz = z0 + z1;

    float d2 = fmaf(fx, fx, fmaf(fy, fy, fz * fz));
    d2 = fmaxf(d2, 1e-24f);
    float r = rsqrtf(d2);
    r = r * fmaf(-0.5f * d2 * r, r, 1.5f);  // one Newton step for the final normalize

    out[3 * n + 0] = fx * r;
    out[3 * n + 1] = fy * r;
    out[3 * n + 2] = fz * r;
}

extern "C" void kernel_launch(void* const* d_in, const int* in_sizes, int n_in,
                              void* d_out, int out_size)
{
    const float* pos = (const float*)d_in[0];
    const float* nbr = (const float*)d_in[1];
    const float* W1  = (const float*)d_in[2];
    const float* b1  = (const float*)d_in[3];
    const float* W2  = (const float*)d_in[4];
    const float* b2  = (const float*)d_in[5];
    const float* W3  = (const float*)d_in[6];
    const float* b3  = (const float*)d_in[7];
    float* out = (float*)d_out;

    int N = in_sizes[0] / 3;  // positions is [N,3]
    int threads = 128;
    int blocks = (N + threads - 1) / threads;
    velvec_kernel<<<blocks, threads>>>(pos, nbr, W1, b1, W2, b2, W3, b3, out, N);
}